// round 7
// baseline (speedup 1.0000x reference)
#include <cuda_runtime.h>

// APMLSparse: x[B,N,3], y[B,M,3] fp32 -> scalar loss. B=4, N=M=4096.
// Per row: d_j = sqrt(max(||x-y_j||^2,1e-12)), e_j=exp(-d_j), Z=sum e_j.
// Kept = d-ascending prefix while exclusive cumulative mass < 0.8*Z (incl.
// crossing entry, p>1e-10 filter). loss += sum_kept e_j*d_j / Z.
//
// R5: two-stage per-thread-private banked histogram quantile search.
//  - stage 1: 32 bins of width 0.5 over d (dynamic smem, 64KB, conflict-free
//    column per thread), filled during the f32x2-packed distance pass.
//  - bin reduce doubles as the zeroing pass (read-then-clear).
//  - stage 2: 32 sub-bins (width 1/64) over the crossing bin only; elements
//    strictly below the crossing bin accumulate e*d immediately.
//  - final band (~35 elems) -> exact O(k^2) rank resolution, no penta needed.
//  - per-thread acc scaled by rcp(Z) per row; single block reduce per CTA.

#define NTH  512
#define NPT  8             // 4096 / NTH
#define RPC  8
#define MPTS 4096
#define NB   32
#define CAP  384
#define HIST_BYTES (NB * NTH * 4)   // 65536

__global__ void apml_zero_out(float* o) { o[0] = 0.0f; }

__device__ __forceinline__ unsigned long long pk2(float lo, float hi) {
    unsigned long long r;
    asm("mov.b64 %0, {%1, %2};" : "=l"(r) : "f"(lo), "f"(hi));
    return r;
}
__device__ __forceinline__ void upk2(unsigned long long v, float& lo, float& hi) {
    asm("mov.b64 {%0, %1}, %2;" : "=f"(lo), "=f"(hi) : "l"(v));
}
__device__ __forceinline__ unsigned long long add2(unsigned long long a, unsigned long long b) {
    unsigned long long r;
    asm("add.rn.f32x2 %0, %1, %2;" : "=l"(r) : "l"(a), "l"(b));
    return r;
}
__device__ __forceinline__ unsigned long long mul2(unsigned long long a, unsigned long long b) {
    unsigned long long r;
    asm("mul.rn.f32x2 %0, %1, %2;" : "=l"(r) : "l"(a), "l"(b));
    return r;
}
__device__ __forceinline__ unsigned long long fma2(unsigned long long a, unsigned long long b,
                                                   unsigned long long c) {
    unsigned long long r;
    asm("fma.rn.f32x2 %0, %1, %2, %3;" : "=l"(r) : "l"(a), "l"(b), "l"(c));
    return r;
}

__global__ __launch_bounds__(NTH, 2)
void apml_kernel(const float* __restrict__ x, const float* __restrict__ y,
                 float* __restrict__ out)
{
    extern __shared__ float hist[];          // NB*NTH floats (64 KB dynamic)
    __shared__ float2 list[CAP];
    __shared__ float  binTot[NB];
    __shared__ float  warpRed[16];
    __shared__ float  s_ctl[8];   // 0:Z 1:T 2:c1(bits) 3:mLo1 4:c2(bits) 5:mLo2 6:rcpZ
    __shared__ int    s_cnt;

    const int tid = threadIdx.x, lane = tid & 31, wid = tid >> 5;
    const int cpb = MPTS / RPC;                    // 512
    const int b = blockIdx.x / cpb;
    const int rowBase = (blockIdx.x % cpb) * RPC;

    // Load 8 y-points per thread, negated and packed as f32x2 pairs.
    unsigned long long nyx[4], nyy[4], nyz[4];
    {
        const float* yb = y + (size_t)b * MPTS * 3;
#pragma unroll
        for (int p = 0; p < 4; p++) {
            int j0 = (2 * p) * NTH + tid;
            int j1 = (2 * p + 1) * NTH + tid;
            nyx[p] = pk2(-yb[j0 * 3 + 0], -yb[j1 * 3 + 0]);
            nyy[p] = pk2(-yb[j0 * 3 + 1], -yb[j1 * 3 + 1]);
            nyz[p] = pk2(-yb[j0 * 3 + 2], -yb[j1 * 3 + 2]);
        }
    }

    // Initial histogram zero (afterwards the reduces keep it clean).
    float4* h4 = (float4*)hist;
#pragma unroll
    for (int i = 0; i < NB * NTH / 4 / NTH; i++)
        h4[tid + i * NTH] = make_float4(0.f, 0.f, 0.f, 0.f);

    float ctaAcc = 0.0f;
    __syncthreads();

    for (int r = 0; r < RPC; r++) {
        const float* xp = x + ((size_t)b * MPTS + rowBase + r) * 3;
        const float x0 = __ldg(xp + 0);
        const float x1 = __ldg(xp + 1);
        const float x2 = __ldg(xp + 2);
        if (tid == 0) s_cnt = 0;

        const unsigned long long x0p = pk2(x0, x0);
        const unsigned long long x1p = pk2(x1, x1);
        const unsigned long long x2p = pk2(x2, x2);

        // ---- pass 1: packed distances, exp, stage-1 histogram ----
        float dreg[NPT];
#pragma unroll
        for (int p = 0; p < 4; p++) {
            unsigned long long dx = add2(x0p, nyx[p]);
            unsigned long long dy = add2(x1p, nyy[p]);
            unsigned long long dz = add2(x2p, nyz[p]);
            unsigned long long sq = fma2(dx, dx, fma2(dy, dy, mul2(dz, dz)));
            float s0, s1;
            upk2(sq, s0, s1);
            {
                float ss = fmaxf(s0, 1e-12f);
                float d = ss * rsqrtf(ss);
                dreg[2 * p] = d;
                float ex = __expf(-d);
                int bin = (int)(2.0f * d);
                bin = bin < (NB - 1) ? bin : (NB - 1);
                hist[bin * NTH + tid] += ex;
            }
            {
                float ss = fmaxf(s1, 1e-12f);
                float d = ss * rsqrtf(ss);
                dreg[2 * p + 1] = d;
                float ex = __expf(-d);
                int bin = (int)(2.0f * d);
                bin = bin < (NB - 1) ? bin : (NB - 1);
                hist[bin * NTH + tid] += ex;
            }
        }
        __syncthreads();

        // ---- reduce stage-1 bins (and zero them): warp w -> bins 2w, 2w+1 ----
#pragma unroll
        for (int q = 0; q < 2; q++) {
            int bb = 2 * wid + q;
            float4* col = (float4*)(hist + bb * NTH);
            float s = 0.f;
#pragma unroll
            for (int i = 0; i < NTH / 4 / 32; i++) {
                float4 v = col[lane + 32 * i];
                s += (v.x + v.y) + (v.z + v.w);
                col[lane + 32 * i] = make_float4(0.f, 0.f, 0.f, 0.f);
            }
#pragma unroll
            for (int o = 16; o; o >>= 1) s += __shfl_xor_sync(0xffffffffu, s, o);
            if (lane == 0) binTot[bb] = s;
        }
        __syncthreads();

        // ---- scan stage 1 (warp 0, 32 lanes = 32 bins) ----
        if (wid == 0) {
            float mm = binTot[lane];
            float incl = mm;
#pragma unroll
            for (int o = 1; o < 32; o <<= 1) {
                float t = __shfl_up_sync(0xffffffffu, incl, o);
                if (lane >= o) incl += t;
            }
            float total = __shfl_sync(0xffffffffu, incl, 31);
            float T = 0.8f * total;
            float excl = incl - mm;
            unsigned bal = __ballot_sync(0xffffffffu, (excl < T) && (incl >= T));
            int c1 = bal ? (__ffs(bal) - 1) : (NB - 1);
            float mlo = __shfl_sync(0xffffffffu, excl, c1);
            if (lane == 0) {
                s_ctl[0] = total;
                s_ctl[1] = T;
                s_ctl[2] = __int_as_float(c1);
                s_ctl[3] = mlo;
                s_ctl[6] = __frcp_rn(total);
            }
        }
        __syncthreads();
        const float Z    = s_ctl[0];
        const float T    = s_ctl[1];
        const int   c1s  = __float_as_int(s_ctl[2]) << 5;   // c1*32
        const float mLo1 = s_ctl[3];
        const float rcpZ = s_ctl[6];

        // ---- stage-2 fill (sub-bins width 1/64) + below-bin kept accumulation ----
        float acc = 0.0f;
#pragma unroll
        for (int k = 0; k < NPT; k++) {
            float d = dreg[k];
            int b2 = (int)(64.0f * d) - c1s;      // exact: 64d, 2d share truncation grid
            if (b2 < 0) {
                float ex = __expf(-d);
                acc = fmaf(ex, d, acc);
            } else if (b2 < NB) {
                float ex = __expf(-d);
                hist[b2 * NTH + tid] += ex;
            }
        }
        __syncthreads();

        // ---- reduce stage-2 bins (and zero them) ----
#pragma unroll
        for (int q = 0; q < 2; q++) {
            int bb = 2 * wid + q;
            float4* col = (float4*)(hist + bb * NTH);
            float s = 0.f;
#pragma unroll
            for (int i = 0; i < NTH / 4 / 32; i++) {
                float4 v = col[lane + 32 * i];
                s += (v.x + v.y) + (v.z + v.w);
                col[lane + 32 * i] = make_float4(0.f, 0.f, 0.f, 0.f);
            }
#pragma unroll
            for (int o = 16; o; o >>= 1) s += __shfl_xor_sync(0xffffffffu, s, o);
            if (lane == 0) binTot[bb] = s;
        }
        __syncthreads();

        // ---- scan stage 2 ----
        if (wid == 0) {
            float mm = binTot[lane];
            float incl = mm;
#pragma unroll
            for (int o = 1; o < 32; o <<= 1) {
                float t = __shfl_up_sync(0xffffffffu, incl, o);
                if (lane >= o) incl += t;
            }
            float excl = incl - mm;
            unsigned bal = __ballot_sync(0xffffffffu,
                                         (mLo1 + excl < T) && (mLo1 + incl >= T));
            int c2 = bal ? (__ffs(bal) - 1) : (NB - 1);   // fp-mismatch fallback
            float mlo2 = mLo1 + __shfl_sync(0xffffffffu, excl, c2);
            if (lane == 0) {
                s_ctl[4] = __int_as_float(c2);
                s_ctl[5] = mlo2;
            }
        }
        __syncthreads();
        const int   c2i  = __float_as_int(s_ctl[4]);
        const float mLo2 = s_ctl[5];
        const float lc   = (float)c1s * 0.015625f;          // crossing-bin low edge
        const float l2f  = (float)(c1s + c2i) * 0.015625f;  // exact fp
        const float h2f  = l2f + 0.015625f;

        // ---- compact: crossing-bin elements below l2f kept; band appended ----
#pragma unroll
        for (int k = 0; k < NPT; k++) {
            float d = dreg[k];
            bool inbin = (d >= lc) && (d < h2f);
            bool kept  = inbin && (d < l2f);
            bool band  = inbin && !kept;
            if (kept) {
                float ex = __expf(-d);
                acc = fmaf(ex, d, acc);
            }
            unsigned mk = __ballot_sync(0xffffffffu, band);
            if (mk) {
                int leader = __ffs(mk) - 1;
                int base = 0;
                if (lane == leader) base = atomicAdd(&s_cnt, __popc(mk));
                base = __shfl_sync(0xffffffffu, base, leader);
                if (band) {
                    int idx = base + __popc(mk & ((1u << lane) - 1u));
                    float ex = __expf(-d);
                    if (idx < CAP) list[idx] = make_float2(d, ex);
                    else           acc = fmaf(ex, d, acc);   // overflow fallback
                }
            }
        }
        __syncthreads();

        // ---- exact O(k^2) rank resolution on the ~35-element band ----
        const int   cnt  = s_cnt < CAP ? s_cnt : CAP;
        const float Trem = T - mLo2;
        const float eThr = 1e-10f * Z;
        for (int i = tid; i < cnt; i += NTH) {
            float2 vi = list[i];
            float rm = 0.f;
            for (int j = 0; j < cnt; j++) {
                float2 vj = list[j];
                rm += ((vj.x < vi.x) || (vj.x == vi.x && j < i)) ? vj.y : 0.f;
            }
            if (rm < Trem && vi.y > eThr) acc = fmaf(vi.y, vi.x, acc);
        }

        // ---- fold row into per-thread accumulator (no per-row block reduce) ----
        ctaAcc = fmaf(acc, rcpZ, ctaAcc);
        // no end-of-row barrier needed: next row's first barrier orders
        // hist writes; list/s_cnt are rewritten only after multiple barriers.
    }

    // ---- one block reduce per CTA ----
#pragma unroll
    for (int o = 16; o; o >>= 1) ctaAcc += __shfl_xor_sync(0xffffffffu, ctaAcc, o);
    if (lane == 0) warpRed[wid] = ctaAcc;
    __syncthreads();
    if (tid == 0) {
        float tot = 0.f;
#pragma unroll
        for (int i = 0; i < 16; i++) tot += warpRed[i];
        atomicAdd(out, tot);
    }
}

extern "C" void kernel_launch(void* const* d_in, const int* in_sizes, int n_in,
                              void* d_out, int out_size)
{
    const float* x = (const float*)d_in[0];
    const float* y = (const float*)d_in[1];
    float* out = (float*)d_out;

    cudaFuncSetAttribute(apml_kernel,
                         cudaFuncAttributeMaxDynamicSharedMemorySize, HIST_BYTES);

    apml_zero_out<<<1, 1>>>(out);
    const int grid = (4 * MPTS) / RPC;   // 2048 CTAs
    apml_kernel<<<grid, NTH, HIST_BYTES>>>(x, y, out);
}